// round 5
// baseline (speedup 1.0000x reference)
#include <cuda_runtime.h>
#include <math.h>

#define BATCH 8192
#define DIM   2048
#define WORDS 64          // 2048 bits / 32 per row
#define NBLK  128         // forward grid
#define BTH   64          // forward block

// ---------------- device scratch (no allocations allowed) ----------------
__device__ float4   g_tab1[256 * 3];     // 8-step products of K matrices
__device__ float4   g_tab2[256 * 3];     // 7 K's + trailing diag(e) for last byte
__device__ float    g_pi[4];
__device__ unsigned g_packed[BATCH * WORDS];
__device__ float    g_partials[NBLK];

// ---------------- 1) precompute 3x3 matrix tables in fp64 ----------------
__global__ void precompute_kernel(const float* __restrict__ T,
                                  const float* __restrict__ E,
                                  const float* __restrict__ S) {
    int c = blockIdx.x * blockDim.x + threadIdx.x;   // 0..511
    double W[3][3], e[2][3];
    for (int i = 0; i < 3; i++) {
        double t0 = T[i * 3 + 0], t1 = T[i * 3 + 1], t2 = T[i * 3 + 2];
        double m = fmax(t0, fmax(t1, t2));
        double s0 = exp(t0 - m), s1 = exp(t1 - m), s2 = exp(t2 - m);
        double Z = s0 + s1 + s2;
        W[i][0] = s0 / Z; W[i][1] = s1 / Z; W[i][2] = s2 / Z;
        double a = E[i * 2 + 0], b = E[i * 2 + 1];
        double mm = fmax(a, b);
        double ea = exp(a - mm), eb = exp(b - mm);
        double Ze = ea + eb;
        e[0][i] = ea / Ze;   // P(obs=0 | state i)
        e[1][i] = eb / Ze;   // P(obs=1 | state i)
    }
    int byte   = c & 255;
    int second = (c >= 256);

    // P = K_{b0},  K_o[i][j] = e_o[i] * W[i][j]   (row-vector convention v' = v.P)
    double P[3][3];
    {
        int b0 = byte & 1;
        for (int i = 0; i < 3; i++)
            for (int j = 0; j < 3; j++)
                P[i][j] = e[b0][i] * W[i][j];
    }
    int nk = second ? 7 : 8;
    for (int t = 1; t < nk; t++) {
        int bt = (byte >> t) & 1;
        double Q[3][3];
        for (int i = 0; i < 3; i++)
            for (int j = 0; j < 3; j++)
                Q[i][j] = P[i][0] * (e[bt][0] * W[0][j])
                        + P[i][1] * (e[bt][1] * W[1][j])
                        + P[i][2] * (e[bt][2] * W[2][j]);
        for (int i = 0; i < 3; i++)
            for (int j = 0; j < 3; j++) P[i][j] = Q[i][j];
    }
    if (second) {   // trailing emission diag for the very last timestep
        int b7 = (byte >> 7) & 1;
        for (int i = 0; i < 3; i++)
            for (int j = 0; j < 3; j++) P[i][j] *= e[b7][j];
    }
    float4* dst = (second ? g_tab2 : g_tab1) + byte * 3;
    for (int i = 0; i < 3; i++)
        dst[i] = make_float4((float)P[i][0], (float)P[i][1], (float)P[i][2], 0.f);

    if (c == 0) {
        double s0 = S[0], s1 = S[1], s2 = S[2];
        double m = fmax(s0, fmax(s1, s2));
        double a = exp(s0 - m), b = exp(s1 - m), d = exp(s2 - m);
        double Z = a + b + d;
        g_pi[0] = (float)(a / Z);
        g_pi[1] = (float)(b / Z);
        g_pi[2] = (float)(d / Z);
        g_pi[3] = 0.f;
    }
}

// ---------------- 2) ballot-pack y (int32 0/1) into bits ----------------
// warp task: 1024 consecutive ints -> 32 words. Reads fully coalesced 128B,
// all 32 loads independent (MLP=32). Final store coalesced 128B per warp.
__global__ void __launch_bounds__(256) pack_kernel(const int* __restrict__ y) {
    int warp_id = (blockIdx.x * blockDim.x + threadIdx.x) >> 5;   // 0..16383
    int lane    = threadIdx.x & 31;
    const int* p = y + (size_t)warp_id * 1024;
    unsigned my = 0;
    #pragma unroll
    for (int r = 0; r < 32; r++) {
        int v = p[r * 32 + lane];
        unsigned b = __ballot_sync(0xFFFFFFFFu, v != 0);
        if (lane == r) my = b;
    }
    g_packed[warp_id * 32 + lane] = my;
}

// ---------------- 3) forward chain: 256 table-driven 3-vec x 3x3 steps ----
__device__ __forceinline__ void mulmat(float& v0, float& v1, float& v2,
                                       const float4* __restrict__ m) {
    float4 r0 = m[0], r1 = m[1], r2 = m[2];
    float n0 = fmaf(v0, r0.x, fmaf(v1, r1.x, v2 * r2.x));
    float n1 = fmaf(v0, r0.y, fmaf(v1, r1.y, v2 * r2.y));
    float n2 = fmaf(v0, r0.z, fmaf(v1, r1.z, v2 * r2.z));
    v0 = n0; v1 = n1; v2 = n2;
}

__device__ __forceinline__ void renorm(float& v0, float& v1, float& v2, int& etot) {
    float s = v0 + v1 + v2;                       // strictly positive
    unsigned eb = __float_as_uint(s) >> 23;       // biased exponent
    etot += (int)eb - 127;
    float sc = __uint_as_float((254u - eb) << 23);// 2^{-e}
    v0 *= sc; v1 *= sc; v2 *= sc;
}

__device__ __forceinline__ void do_word(unsigned w, float& v0, float& v1, float& v2,
                                        int& etot, const float4* __restrict__ tab) {
    #pragma unroll
    for (int k = 0; k < 32; k += 16) {
        mulmat(v0, v1, v2, tab + ((w >> k) & 255u) * 3);
        mulmat(v0, v1, v2, tab + ((w >> (k + 8)) & 255u) * 3);
        renorm(v0, v1, v2, etot);                 // every 2 groups: short dep chain
    }
}

__global__ void __launch_bounds__(BTH) forward_kernel() {
    __shared__ float4 t1[768];
    __shared__ float4 t2[768];
    __shared__ float  red[BTH];
    int tid = threadIdx.x;
    for (int i = tid; i < 768; i += BTH) { t1[i] = g_tab1[i]; t2[i] = g_tab2[i]; }
    __syncthreads();

    int row = blockIdx.x * BTH + tid;
    const uint4* pw = (const uint4*)(g_packed + row * WORDS);   // 16 x uint4

    float v0 = g_pi[0], v1 = g_pi[1], v2 = g_pi[2];
    int etot = 0;
    uint4 cur = pw[0];
    #pragma unroll 1
    for (int q = 0; q < 15; q++) {
        uint4 nxt = pw[q + 1];                    // prefetch one uint4 ahead
        do_word(cur.x, v0, v1, v2, etot, t1);
        do_word(cur.y, v0, v1, v2, etot, t1);
        do_word(cur.z, v0, v1, v2, etot, t1);
        do_word(cur.w, v0, v1, v2, etot, t1);
        cur = nxt;
    }
    // last uint4: final byte uses table2 (7 K's + trailing emission diag)
    do_word(cur.x, v0, v1, v2, etot, t1);
    do_word(cur.y, v0, v1, v2, etot, t1);
    do_word(cur.z, v0, v1, v2, etot, t1);
    {
        unsigned w = cur.w;
        mulmat(v0, v1, v2, t1 + (w         & 255u) * 3);
        mulmat(v0, v1, v2, t1 + ((w >> 8)  & 255u) * 3);
        renorm(v0, v1, v2, etot);
        mulmat(v0, v1, v2, t1 + ((w >> 16) & 255u) * 3);
        mulmat(v0, v1, v2, t2 + ((w >> 24) & 255u) * 3);
        renorm(v0, v1, v2, etot);
    }
    float logp = logf(v0 + v1 + v2) + (float)etot * 0.69314718055994530942f;

    red[tid] = logp;
    __syncthreads();
    #pragma unroll
    for (int off = BTH / 2; off > 0; off >>= 1) {
        if (tid < off) red[tid] += red[tid + off];
        __syncthreads();
    }
    if (tid == 0) g_partials[blockIdx.x] = red[0];
}

// ---------------- 4) deterministic final reduction (fp64) ----------------
__global__ void finalize_kernel(float* __restrict__ out) {
    __shared__ double sd[NBLK];
    int t = threadIdx.x;
    sd[t] = (double)g_partials[t];
    __syncthreads();
    #pragma unroll
    for (int o = NBLK / 2; o > 0; o >>= 1) {
        if (t < o) sd[t] += sd[t + o];
        __syncthreads();
    }
    if (t == 0) out[0] = (float)(sd[0] / (double)BATCH);
}

// ---------------- launch ----------------
extern "C" void kernel_launch(void* const* d_in, const int* in_sizes, int n_in,
                              void* d_out, int out_size) {
    const int*   y = (const int*)d_in[0];
    const float* T = (const float*)d_in[1];
    const float* E = (const float*)d_in[2];
    const float* S = (const float*)d_in[3];

    precompute_kernel<<<2, 256>>>(T, E, S);
    pack_kernel<<<(BATCH * DIM / 1024) / 8, 256>>>(y);   // 2048 blocks x 8 warps
    forward_kernel<<<NBLK, BTH>>>();
    finalize_kernel<<<1, NBLK>>>((float*)d_out);
}